// round 2
// baseline (speedup 1.0000x reference)
#include <cuda_runtime.h>
#include <cuda_bf16.h>
#include <cstdint>

// ---------------------------------------------------------------------------
// Simplicial attention, restructured:
//   For each source (K=V in all three):
//     Z_i   = sum_j exp(s_ij)                (no max needed: s <= ~22)
//     u_ij  = expm1( exp(s_ij)/Z_i * mask )  (u in [0, e-1], small)
//     out_i = (colsum(V) + sum_j u_ij V_j) / (M + sum_j u_ij)
//   Final = (out^0 + out^1 + out^2) / 3
// ---------------------------------------------------------------------------

#define D        256
#define BM       64
#define BN       64
#define NTHREADS 256
#define SQ_LD    264   // 256 + 8 bf16 pad -> 528B rows, conflict-free ldmatrix
#define SU_LD    72    // 64 + 8 pad
#define NQ       8192
#define SCALE    0.0625f   // 1/sqrt(256)

#define SMEM_TOTAL 81408

// scratch: bf16 copies of H (rows 0..8191), H_low (8192..12287), H_high (12288..28671)
__device__ __align__(128) __nv_bfloat16 g_kv[28672 * 256];
__device__ __align__(128) float g_vsum[3 * 256];

// ---------------------------------------------------------------------------
__global__ void init_kernel(float* __restrict__ out) {
    int idx = blockIdx.x * blockDim.x + threadIdx.x;
    if (idx < NQ * D) out[idx] = 0.0f;
    if (idx < 3 * 256) g_vsum[idx] = 0.0f;
}

// convert fp32 -> bf16 and accumulate column sums (V column sums are exact fp32)
__global__ void convert_kernel(const float* __restrict__ H,
                               const float* __restrict__ Hlow,
                               const float* __restrict__ Hhigh) {
    int r0  = blockIdx.x * 32;
    int col = threadIdx.x;             // 256 threads = 256 columns
    float acc = 0.0f;
    #pragma unroll 4
    for (int i = 0; i < 32; i++) {
        int r = r0 + i;
        float v;
        if (r < 8192)       v = H[(long)r * D + col];
        else if (r < 12288) v = Hlow[(long)(r - 8192) * D + col];
        else                v = Hhigh[(long)(r - 12288) * D + col];
        g_kv[(long)r * D + col] = __float2bfloat16(v);
        acc += v;
    }
    int src = (r0 < 8192) ? 0 : (r0 < 12288 ? 1 : 2);
    atomicAdd(&g_vsum[src * 256 + col], acc);
}

// ---------------------------------------------------------------------------
__device__ __forceinline__ uint32_t smem_u32(const void* p) {
    return (uint32_t)__cvta_generic_to_shared(p);
}
__device__ __forceinline__ void ldsm_x4(uint32_t& r0, uint32_t& r1,
                                        uint32_t& r2, uint32_t& r3, uint32_t addr) {
    asm volatile("ldmatrix.sync.aligned.m8n8.x4.shared.b16 {%0,%1,%2,%3}, [%4];\n"
                 : "=r"(r0), "=r"(r1), "=r"(r2), "=r"(r3) : "r"(addr));
}
__device__ __forceinline__ void ldsm_x4_t(uint32_t& r0, uint32_t& r1,
                                          uint32_t& r2, uint32_t& r3, uint32_t addr) {
    asm volatile("ldmatrix.sync.aligned.m8n8.x4.trans.shared.b16 {%0,%1,%2,%3}, [%4];\n"
                 : "=r"(r0), "=r"(r1), "=r"(r2), "=r"(r3) : "r"(addr));
}
__device__ __forceinline__ void mma_bf16(float* d, const uint32_t* a, const uint32_t* b) {
    asm volatile(
        "mma.sync.aligned.m16n8k16.row.col.f32.bf16.bf16.f32 "
        "{%0,%1,%2,%3}, {%4,%5,%6,%7}, {%8,%9}, {%0,%1,%2,%3};\n"
        : "+f"(d[0]), "+f"(d[1]), "+f"(d[2]), "+f"(d[3])
        : "r"(a[0]), "r"(a[1]), "r"(a[2]), "r"(a[3]), "r"(b[0]), "r"(b[1]));
}

// ---------------------------------------------------------------------------
__global__ __launch_bounds__(NTHREADS, 2)
void attn_kernel(const int* __restrict__ L,
                 const int* __restrict__ Blow,
                 const int* __restrict__ Bhigh,
                 float* __restrict__ out) {
    extern __shared__ char smem[];
    __nv_bfloat16* sQ = (__nv_bfloat16*)smem;                    // 64 x 264
    __nv_bfloat16* sK = sQ + BM * SQ_LD;                         // 64 x 264
    __nv_bfloat16* sU = sK + BN * SQ_LD;                         // 64 x 72
    unsigned char* sM = (unsigned char*)(sU + BM * SU_LD);       // 64 x 64
    float*         sZ = (float*)(sM + BM * BN);                  // 64
    float*       sDen = sZ + 64;                                 // 64

    // block -> (source, query tile); longest source first for wave balance
    int bid = blockIdx.x;
    int src, qt;
    if (bid < 128)      { src = 2; qt = bid; }
    else if (bid < 256) { src = 0; qt = bid - 128; }
    else                { src = 1; qt = bid - 256; }

    const int* mask; int M; long koff; bool transposed;
    if (src == 0)      { M = 8192;  koff = 0;            mask = L;     transposed = false; }
    else if (src == 1) { M = 4096;  koff = 8192L * D;    mask = Blow;  transposed = true;  }
    else               { M = 16384; koff = 12288L * D;   mask = Bhigh; transposed = false; }
    int nkt = M / BN;
    int i0  = qt * BM;

    int tid  = threadIdx.x;
    int lane = tid & 31;
    int wid  = tid >> 5;
    int mi   = wid & 3;   // m-slice (16 rows)
    int ni   = wid >> 2;  // n-slice (32 S-cols / 128 out-cols)

    // load Q tile (bf16) once
    {
        const uint4* gq = (const uint4*)(g_kv + (long)i0 * D);
        for (int idx = tid; idx < BM * 32; idx += NTHREADS) {
            int r = idx >> 5, c = idx & 31;
            *(uint4*)(sQ + r * SQ_LD + c * 8) = gq[r * 32 + c];
        }
    }
    if (tid < 64) { sZ[tid] = 0.0f; sDen[tid] = 0.0f; }
    __syncthreads();

    uint32_t sQb = smem_u32(sQ), sKb = smem_u32(sK), sUb = smem_u32(sU);
    int lr16  = lane & 15;            // row within 16-row ldmatrix tile
    int lc8   = (lane >> 4) << 3;     // 0 or 8 (col group)
    int brow  = (lane & 7) + ((lane & 16) >> 1);  // B (non-trans) n-row
    int bcol8 = lane & 8;                          // B (non-trans) k-col group
    int g     = lane >> 2;            // row group within 8
    int c2    = (lane & 3) << 1;      // col pair

    uint32_t aAddrBase = sQb + (uint32_t)(((mi * 16 + lr16) * SQ_LD + lc8) * 2);

    // ================= PASS 1: Z_i = sum exp(s) =================
    float accZ0 = 0.0f, accZ1 = 0.0f;
    for (int jt = 0; jt < nkt; jt++) {
        const uint4* gk = (const uint4*)(g_kv + koff + (long)jt * BN * D);
        for (int idx = tid; idx < BN * 32; idx += NTHREADS) {
            int r = idx >> 5, cc = idx & 31;
            *(uint4*)(sK + r * SQ_LD + cc * 8) = gk[r * 32 + cc];
        }
        __syncthreads();

        float d[4][4];
        #pragma unroll
        for (int f = 0; f < 4; f++) { d[f][0]=0.f; d[f][1]=0.f; d[f][2]=0.f; d[f][3]=0.f; }
        #pragma unroll
        for (int kk = 0; kk < 16; kk++) {
            uint32_t a[4];
            ldsm_x4(a[0], a[1], a[2], a[3], aAddrBase + kk * 32);
            #pragma unroll
            for (int j = 0; j < 2; j++) {
                uint32_t b[4];
                uint32_t ba = sKb + (uint32_t)(((ni * 32 + j * 16 + brow) * SQ_LD
                                                + kk * 16 + bcol8) * 2);
                ldsm_x4(b[0], b[1], b[2], b[3], ba);
                mma_bf16(d[2 * j],     a, b);
                mma_bf16(d[2 * j + 1], a, b + 2);
            }
        }
        #pragma unroll
        for (int f = 0; f < 4; f++) {
            accZ0 += __expf(d[f][0] * SCALE) + __expf(d[f][1] * SCALE);
            accZ1 += __expf(d[f][2] * SCALE) + __expf(d[f][3] * SCALE);
        }
        __syncthreads();
    }
    accZ0 += __shfl_xor_sync(~0u, accZ0, 1); accZ0 += __shfl_xor_sync(~0u, accZ0, 2);
    accZ1 += __shfl_xor_sync(~0u, accZ1, 1); accZ1 += __shfl_xor_sync(~0u, accZ1, 2);
    if ((lane & 3) == 0) {
        atomicAdd(&sZ[mi * 16 + g],     accZ0);
        atomicAdd(&sZ[mi * 16 + g + 8], accZ1);
    }
    __syncthreads();
    float rcpZ0 = __frcp_rn(sZ[mi * 16 + g]);
    float rcpZ1 = __frcp_rn(sZ[mi * 16 + g + 8]);

    // ================= PASS 2: U = expm1(p*mask); acc += U @ V =================
    float acc[16][4];
    #pragma unroll
    for (int f = 0; f < 16; f++) { acc[f][0]=0.f; acc[f][1]=0.f; acc[f][2]=0.f; acc[f][3]=0.f; }
    float accD0 = 0.0f, accD1 = 0.0f;

    for (int jt = 0; jt < nkt; jt++) {
        const uint4* gk = (const uint4*)(g_kv + koff + (long)jt * BN * D);
        for (int idx = tid; idx < BN * 32; idx += NTHREADS) {
            int r = idx >> 5, cc = idx & 31;
            *(uint4*)(sK + r * SQ_LD + cc * 8) = gk[r * 32 + cc];
        }
        int j0 = jt * BN;
        if (!transposed) {
            for (int idx = tid; idx < BM * BN; idx += NTHREADS) {
                int r = idx >> 6, cc = idx & 63;
                sM[idx] = (mask[(long)(i0 + r) * M + (j0 + cc)] != 0);
            }
        } else {
            for (int idx = tid; idx < BM * BN; idx += NTHREADS) {
                int kr = idx >> 6, qc = idx & 63;
                sM[qc * 64 + kr] = (mask[(long)(j0 + kr) * NQ + (i0 + qc)] != 0);
            }
        }
        __syncthreads();

        float d[4][4];
        #pragma unroll
        for (int f = 0; f < 4; f++) { d[f][0]=0.f; d[f][1]=0.f; d[f][2]=0.f; d[f][3]=0.f; }
        #pragma unroll
        for (int kk = 0; kk < 16; kk++) {
            uint32_t a[4];
            ldsm_x4(a[0], a[1], a[2], a[3], aAddrBase + kk * 32);
            #pragma unroll
            for (int j = 0; j < 2; j++) {
                uint32_t b[4];
                uint32_t ba = sKb + (uint32_t)(((ni * 32 + j * 16 + brow) * SQ_LD
                                                + kk * 16 + bcol8) * 2);
                ldsm_x4(b[0], b[1], b[2], b[3], ba);
                mma_bf16(d[2 * j],     a, b);
                mma_bf16(d[2 * j + 1], a, b + 2);
            }
        }
        int m0 = mi * 16 + g;
        #pragma unroll
        for (int f = 0; f < 4; f++) {
            int n = ni * 32 + f * 8 + c2;
            float u0 = 0.f, u1 = 0.f, u2 = 0.f, u3 = 0.f;
            float e;
            e = __expf(d[f][0] * SCALE); if (sM[m0 * 64 + n])           u0 = __expf(e * rcpZ0) - 1.0f;
            e = __expf(d[f][1] * SCALE); if (sM[m0 * 64 + n + 1])       u1 = __expf(e * rcpZ0) - 1.0f;
            e = __expf(d[f][2] * SCALE); if (sM[(m0 + 8) * 64 + n])     u2 = __expf(e * rcpZ1) - 1.0f;
            e = __expf(d[f][3] * SCALE); if (sM[(m0 + 8) * 64 + n + 1]) u3 = __expf(e * rcpZ1) - 1.0f;
            accD0 += u0 + u1;
            accD1 += u2 + u3;
            *(__nv_bfloat162*)(sU + m0 * SU_LD + n)       = __floats2bfloat162_rn(u0, u1);
            *(__nv_bfloat162*)(sU + (m0 + 8) * SU_LD + n) = __floats2bfloat162_rn(u2, u3);
        }
        __syncthreads();

        // PV: acc[m 16 rows][n 128 cols] += U[m][k64] @ V[k64][n]
        #pragma unroll
        for (int kk = 0; kk < 4; kk++) {
            uint32_t a[4];
            ldsm_x4(a[0], a[1], a[2], a[3],
                    sUb + (uint32_t)(((mi * 16 + lr16) * SU_LD + kk * 16 + lc8) * 2));
            #pragma unroll
            for (int j = 0; j < 8; j++) {
                uint32_t b[4];
                ldsm_x4_t(b[0], b[1], b[2], b[3],
                          sKb + (uint32_t)(((kk * 16 + lr16) * SQ_LD
                                            + ni * 128 + j * 16 + lc8) * 2));
                mma_bf16(acc[2 * j],     a, b);
                mma_bf16(acc[2 * j + 1], a, b + 2);
            }
        }
        __syncthreads();
    }

    accD0 += __shfl_xor_sync(~0u, accD0, 1); accD0 += __shfl_xor_sync(~0u, accD0, 2);
    accD1 += __shfl_xor_sync(~0u, accD1, 1); accD1 += __shfl_xor_sync(~0u, accD1, 2);
    if ((lane & 3) == 0) {
        atomicAdd(&sDen[mi * 16 + g],     accD0);
        atomicAdd(&sDen[mi * 16 + g + 8], accD1);
    }
    __syncthreads();

    // epilogue: out += (vsum + acc) / (M + den) / 3
    float inv0 = 1.0f / ((float)M + sDen[mi * 16 + g]);
    float inv1 = 1.0f / ((float)M + sDen[mi * 16 + g + 8]);
    const float third = 1.0f / 3.0f;
    inv0 *= third; inv1 *= third;
    int mg = i0 + mi * 16 + g;
    #pragma unroll
    for (int f = 0; f < 16; f++) {
        int n = ni * 128 + f * 8 + c2;
        float vs0 = g_vsum[src * 256 + n];
        float vs1 = g_vsum[src * 256 + n + 1];
        atomicAdd(&out[(long)mg * D + n],           (vs0 + acc[f][0]) * inv0);
        atomicAdd(&out[(long)mg * D + n + 1],       (vs1 + acc[f][1]) * inv0);
        atomicAdd(&out[(long)(mg + 8) * D + n],     (vs0 + acc[f][2]) * inv1);
        atomicAdd(&out[(long)(mg + 8) * D + n + 1], (vs1 + acc[f][3]) * inv1);
    }
}

// ---------------------------------------------------------------------------
extern "C" void kernel_launch(void* const* d_in, const int* in_sizes, int n_in,
                              void* d_out, int out_size) {
    const int*   L     = (const int*)d_in[0];
    const float* H     = (const float*)d_in[1];
    const int*   Blow  = (const int*)d_in[2];
    const float* Hlow  = (const float*)d_in[3];
    const int*   Bhigh = (const int*)d_in[4];
    const float* Hhigh = (const float*)d_in[5];
    float* out = (float*)d_out;

    cudaFuncSetAttribute(attn_kernel,
                         cudaFuncAttributeMaxDynamicSharedMemorySize, SMEM_TOTAL);

    init_kernel<<<(NQ * D + 255) / 256, 256>>>(out);
    convert_kernel<<<28672 / 32, 256>>>(H, Hlow, Hhigh);
    attn_kernel<<<384, NTHREADS, SMEM_TOTAL>>>(L, Blow, Bhigh, out);
}

// round 8
// speedup vs baseline: 2.0536x; 2.0536x over previous
#include <cuda_runtime.h>
#include <cuda_bf16.h>
#include <cstdint>

// ============================================================================
// Simplicial attention, single-pass linearized, CTA-local normalization.
// Per source (K=V):
//   Z_i = sum_j exp(s_ij)         (unmasked)
//   u_ij ~= (e_ij/Z_i) m_ij       (order-1; src0 diagonal exact via expm1)
//   out += [ (colsum(V) + (E.m)@V / Z + u_ii v_i) / (M + sum(E.m)/Z + u_ii) ]/3
// CTA = (64-row query tile, source); owns the full key range of its source,
// so Z/t1/diag are CTA-local and the contribution goes straight into out.
// ============================================================================

#define D      256
#define QR     64
#define KT     64
#define NTH    256
#define NQ     8192
#define SCALE  0.0625f
#define QLD    264
#define KLD    264
#define ULD    72

#define SQ_OFF  0
#define SQ_SZ   (QR * QLD * 2)            // 33792
#define K_OFF   SQ_SZ
#define K_SZ    (KT * KLD * 2)            // 33792 x2
#define U_OFF   (K_OFF + 2 * K_SZ)        // 101376
#define U_SZ    (QR * ULD * 2)            // 9216
#define ZR_OFF  (U_OFF + U_SZ)            // 110592
#define DR_OFF  (ZR_OFF + 256)
#define EII_OFF (DR_OFF + 256)
#define SMEM_TOTAL (EII_OFF + 256)        // 111360 -> 2 CTAs/SM

// ---------------------------------------------------------------------------
__device__ __align__(128) __nv_bfloat16 g_kv[28672 * 256];   // 14.7 MB
__device__ __align__(128) float    g_vsum[3 * 256];
__device__ __align__(128) uint32_t g_mb1[8192L * 128];       // 4 MB, B_low^T bits

__device__ __forceinline__ uint32_t smem_u32(const void* p) {
    return (uint32_t)__cvta_generic_to_shared(p);
}
__device__ __forceinline__ void cp16(uint32_t dst, const void* src) {
    asm volatile("cp.async.cg.shared.global [%0], [%1], 16;" :: "r"(dst), "l"(src));
}
#define CP_COMMIT() asm volatile("cp.async.commit_group;" ::: "memory")
#define CP_WAIT1()  asm volatile("cp.async.wait_group 1;" ::: "memory")

__device__ __forceinline__ void ldsm_x4(uint32_t& r0, uint32_t& r1,
                                        uint32_t& r2, uint32_t& r3, uint32_t addr) {
    asm volatile("ldmatrix.sync.aligned.m8n8.x4.shared.b16 {%0,%1,%2,%3}, [%4];\n"
                 : "=r"(r0), "=r"(r1), "=r"(r2), "=r"(r3) : "r"(addr));
}
__device__ __forceinline__ void ldsm_x4_t(uint32_t& r0, uint32_t& r1,
                                          uint32_t& r2, uint32_t& r3, uint32_t addr) {
    asm volatile("ldmatrix.sync.aligned.m8n8.x4.trans.shared.b16 {%0,%1,%2,%3}, [%4];\n"
                 : "=r"(r0), "=r"(r1), "=r"(r2), "=r"(r3) : "r"(addr));
}
__device__ __forceinline__ void mma_bf16(float* d, const uint32_t* a, const uint32_t* b) {
    asm volatile(
        "mma.sync.aligned.m16n8k16.row.col.f32.bf16.bf16.f32 "
        "{%0,%1,%2,%3}, {%4,%5,%6,%7}, {%8,%9}, {%0,%1,%2,%3};\n"
        : "+f"(d[0]), "+f"(d[1]), "+f"(d[2]), "+f"(d[3])
        : "r"(a[0]), "r"(a[1]), "r"(a[2]), "r"(a[3]), "r"(b[0]), "r"(b[1]));
}

// ---------------------------------------------------------------------------
__global__ void init_kernel(float* __restrict__ out) {
    int idx = blockIdx.x * 256 + threadIdx.x;
    if (idx < NQ * D) out[idx] = 0.0f;
    if (idx < 3 * 256) g_vsum[idx] = 0.0f;
}

__global__ void convert_kernel(const float* __restrict__ H,
                               const float* __restrict__ Hlow,
                               const float* __restrict__ Hhigh) {
    int r0 = blockIdx.x * 32, col = threadIdx.x;
    float acc = 0.0f;
    #pragma unroll 4
    for (int i = 0; i < 32; i++) {
        int r = r0 + i;
        float v;
        if (r < 8192)       v = H[(long)r * D + col];
        else if (r < 12288) v = Hlow[(long)(r - 8192) * D + col];
        else                v = Hhigh[(long)(r - 12288) * D + col];
        g_kv[(long)r * D + col] = __float2bfloat16(v);
        acc += v;
    }
    int src = (r0 < 8192) ? 0 : (r0 < 12288 ? 1 : 2);
    atomicAdd(&g_vsum[src * 256 + col], acc);
}

// pack B_low[4096][8192] transposed -> g_mb1[8192 rows][128 words]
__global__ void pack_T_kernel(const int* __restrict__ B) {
    __shared__ int sm[32 * 33];
    int kt = blockIdx.x & 127, it = blockIdx.x >> 7;
    int k0 = kt * 32, i0 = it * 32;
    int tid = threadIdx.x;
    #pragma unroll
    for (int s = 0; s < 4; s++) {
        int idx = tid + s * 256;
        int r = idx >> 5, c = idx & 31;
        sm[r * 33 + c] = B[(long)(k0 + r) * NQ + i0 + c];
    }
    __syncthreads();
    int w = tid >> 5, lane = tid & 31;
    #pragma unroll
    for (int q = 0; q < 4; q++) {
        int i = w * 4 + q;
        uint32_t word = __ballot_sync(0xffffffffu, sm[lane * 33 + i] != 0);
        if (lane == 0) g_mb1[(long)(i0 + i) * 128 + kt] = word;
    }
}

// ---------------------------------------------------------------------------
__global__ __launch_bounds__(NTH, 2)
void attn_kernel(const int* __restrict__ L,
                 const int* __restrict__ Bhigh,
                 float* __restrict__ out) {
    extern __shared__ char smem[];
    uint32_t sb = smem_u32(smem);
    const uint32_t sQ = sb + SQ_OFF;
    __nv_bfloat16* sQp = (__nv_bfloat16*)smem;
    __nv_bfloat16* sUp = (__nv_bfloat16*)(smem + U_OFF);
    float* sZr = (float*)(smem + ZR_OFF);
    float* sDr = (float*)(smem + DR_OFF);
    float* sE  = (float*)(smem + EII_OFF);

    // bid<128: src2 (256 tiles, longest first); 128..255: src0; 256..: src1
    int bid = blockIdx.x;
    int src, qt, ntiles, kvrow0, Mi, W;
    const int* mask;
    if (bid < 128)      { src = 2; qt = bid;       ntiles = 256; kvrow0 = 12288; Mi = 16384; W = 16384; mask = Bhigh; }
    else if (bid < 256) { src = 0; qt = bid - 128; ntiles = 128; kvrow0 = 0;     Mi = 8192;  W = 8192;  mask = L; }
    else                { src = 1; qt = bid - 256; ntiles = 64;  kvrow0 = 8192;  Mi = 4096;  W = 0;     mask = L; }
    int i0 = qt * QR;

    int tid = threadIdx.x, lane = tid & 31, w = tid >> 5;
    int mi = w & 3, ni = w >> 2;
    int g = lane >> 2, c2 = (lane & 3) << 1;
    int lr16 = lane & 15, lc8 = (lane >> 4) << 3;
    int brow = (lane & 7) + ((lane & 16) >> 1), bcol8 = lane & 8;
    int m0 = mi * 16 + g;

    if (tid < QR) { sZr[tid] = 0.0f; sDr[tid] = 0.0f; }

    // ---- prologue: Q + K0 group, K1 group
    {
        const char* gq = (const char*)(g_kv + (long)i0 * D);
        #pragma unroll
        for (int i = 0; i < 8; i++) {
            int idx = tid + i * NTH;
            int r = idx >> 5, cc = (idx & 31) << 3;
            cp16(sQ + (uint32_t)((r * QLD + cc) * 2), gq + ((long)r * D + cc) * 2);
        }
        const char* gk = (const char*)(g_kv + (long)kvrow0 * D);
        #pragma unroll
        for (int i = 0; i < 8; i++) {
            int idx = tid + i * NTH;
            int k = idx >> 5, cc = (idx & 31) << 3;
            cp16(sb + K_OFF + (uint32_t)((k * KLD + cc) * 2), gk + ((long)k * D + cc) * 2);
        }
        CP_COMMIT();
        const char* gk1 = (const char*)(g_kv + (long)(kvrow0 + KT) * D);
        #pragma unroll
        for (int i = 0; i < 8; i++) {
            int idx = tid + i * NTH;
            int k = idx >> 5, cc = (idx & 31) << 3;
            cp16(sb + K_OFF + K_SZ + (uint32_t)((k * KLD + cc) * 2), gk1 + ((long)k * D + cc) * 2);
        }
        CP_COMMIT();
    }

    float zacc0 = 0.f, zacc1 = 0.f, t1acc0 = 0.f, t1acc1 = 0.f;
    float acc[16][4];
    #pragma unroll
    for (int f = 0; f < 16; f++) { acc[f][0]=0.f; acc[f][1]=0.f; acc[f][2]=0.f; acc[f][3]=0.f; }

    uint32_t aBase = sQ + (uint32_t)(((mi * 16 + lr16) * QLD + lc8) * 2);
    uint32_t sUo = sb + U_OFF;
    // mask row base pointers (int path)
    const int* mr0 = mask + (long)(i0 + m0) * W + ni * 32 + c2;
    const int* mr1 = mask + (long)(i0 + m0 + 8) * W + ni * 32 + c2;
    const uint32_t* br0 = g_mb1 + (long)(i0 + m0) * 128;
    const uint32_t* br1 = g_mb1 + (long)(i0 + m0 + 8) * 128;

    for (int j = 0; j < ntiles; j++) {
        CP_WAIT1();
        __syncthreads();
        uint32_t kb = sb + K_OFF + (j & 1) * K_SZ;

        // ---- mask loads (issue early; overlap S-GEMM)
        int2 ma[4], mb[4];
        uint64_t bt0 = 0, bt1 = 0;
        if (src == 1) {
            bt0 = *(const uint64_t*)(br0 + j * 2);
            bt1 = *(const uint64_t*)(br1 + j * 2);
        } else {
            #pragma unroll
            for (int f = 0; f < 4; f++) {
                ma[f] = *(const int2*)(mr0 + j * 64 + f * 8);
                mb[f] = *(const int2*)(mr1 + j * 64 + f * 8);
            }
        }

        // ---- S = Q K^T (64x64), round-0 proven fragment path
        float d[4][4];
        #pragma unroll
        for (int f = 0; f < 4; f++) { d[f][0]=0.f; d[f][1]=0.f; d[f][2]=0.f; d[f][3]=0.f; }
        #pragma unroll
        for (int kk = 0; kk < 16; kk++) {
            uint32_t a[4];
            ldsm_x4(a[0], a[1], a[2], a[3], aBase + kk * 32);
            #pragma unroll
            for (int jj = 0; jj < 2; jj++) {
                uint32_t b[4];
                uint32_t ba = kb + (uint32_t)(((ni * 32 + jj * 16 + brow) * KLD
                                               + kk * 16 + bcol8) * 2);
                ldsm_x4(b[0], b[1], b[2], b[3], ba);
                mma_bf16(d[2 * jj],     a, b);
                mma_bf16(d[2 * jj + 1], a, b + 2);
            }
        }

        // ---- e = exp(s*scale); w = e*mask; stash diag e (src0, tile qt)
        bool diagTile = (src == 0) && (j == qt);
        #pragma unroll
        for (int f = 0; f < 4; f++) {
            int n = ni * 32 + f * 8 + c2;
            float e0 = __expf(d[f][0] * SCALE);
            float e1 = __expf(d[f][1] * SCALE);
            float e2 = __expf(d[f][2] * SCALE);
            float e3 = __expf(d[f][3] * SCALE);
            zacc0 += e0 + e1;
            zacc1 += e2 + e3;
            bool b00, b01, b10, b11;
            if (src == 1) {
                b00 = (bt0 >> n) & 1;  b01 = (bt0 >> (n + 1)) & 1;
                b10 = (bt1 >> n) & 1;  b11 = (bt1 >> (n + 1)) & 1;
            } else {
                b00 = ma[f].x != 0;  b01 = ma[f].y != 0;
                b10 = mb[f].x != 0;  b11 = mb[f].y != 0;
            }
            if (diagTile) {
                if (m0 == n)         { sE[m0]     = b00 ? e0 : 0.f; b00 = false; }
                if (m0 == n + 1)     { sE[m0]     = b01 ? e1 : 0.f; b01 = false; }
                if (m0 + 8 == n)     { sE[m0 + 8] = b10 ? e2 : 0.f; b10 = false; }
                if (m0 + 8 == n + 1) { sE[m0 + 8] = b11 ? e3 : 0.f; b11 = false; }
            }
            float w0 = b00 ? e0 : 0.f, w1 = b01 ? e1 : 0.f;
            float w2 = b10 ? e2 : 0.f, w3 = b11 ? e3 : 0.f;
            t1acc0 += w0 + w1;
            t1acc1 += w2 + w3;
            *(__nv_bfloat162*)(sUp + m0 * ULD + n)       = __floats2bfloat162_rn(w0, w1);
            *(__nv_bfloat162*)(sUp + (m0 + 8) * ULD + n) = __floats2bfloat162_rn(w2, w3);
        }
        __syncthreads();

        // ---- T1 += W @ V  (V = same K tile), round-0 proven PV path
        #pragma unroll
        for (int kk = 0; kk < 4; kk++) {
            uint32_t a[4];
            ldsm_x4(a[0], a[1], a[2], a[3],
                    sUo + (uint32_t)(((mi * 16 + lr16) * ULD + kk * 16 + lc8) * 2));
            #pragma unroll
            for (int j2 = 0; j2 < 8; j2++) {
                uint32_t b[4];
                ldsm_x4_t(b[0], b[1], b[2], b[3],
                          kb + (uint32_t)(((kk * 16 + lr16) * KLD
                                           + ni * 128 + j2 * 16 + lc8) * 2));
                mma_bf16(acc[2 * j2],     a, b);
                mma_bf16(acc[2 * j2 + 1], a, b + 2);
            }
        }
        __syncthreads();

        // ---- refill buffer (j&1) with tile j+2
        if (j + 2 < ntiles) {
            const char* gk = (const char*)(g_kv + (long)(kvrow0 + (j + 2) * KT) * D);
            uint32_t dst = sb + K_OFF + (j & 1) * K_SZ;
            #pragma unroll
            for (int i = 0; i < 8; i++) {
                int idx = tid + i * NTH;
                int k = idx >> 5, cc = (idx & 31) << 3;
                cp16(dst + (uint32_t)((k * KLD + cc) * 2), gk + ((long)k * D + cc) * 2);
            }
        }
        CP_COMMIT();
    }

    // ---- epilogue: CTA-local Z/t1 reduction, then add contribution to out
    zacc0 += __shfl_xor_sync(~0u, zacc0, 1); zacc0 += __shfl_xor_sync(~0u, zacc0, 2);
    zacc1 += __shfl_xor_sync(~0u, zacc1, 1); zacc1 += __shfl_xor_sync(~0u, zacc1, 2);
    t1acc0 += __shfl_xor_sync(~0u, t1acc0, 1); t1acc0 += __shfl_xor_sync(~0u, t1acc0, 2);
    t1acc1 += __shfl_xor_sync(~0u, t1acc1, 1); t1acc1 += __shfl_xor_sync(~0u, t1acc1, 2);
    if ((lane & 3) == 0) {
        atomicAdd(&sZr[m0],     zacc0);
        atomicAdd(&sZr[m0 + 8], zacc1);
        atomicAdd(&sDr[m0],     t1acc0);
        atomicAdd(&sDr[m0 + 8], t1acc1);
    }
    __syncthreads();

    float rz0 = 1.0f / sZr[m0], rz1 = 1.0f / sZr[m0 + 8];
    float Mf = (float)Mi;
    float den0 = Mf + sDr[m0] * rz0, den1 = Mf + sDr[m0 + 8] * rz1;
    float u0 = 0.f, u1 = 0.f;
    if (src == 0) {
        float s0 = sE[m0];     if (s0 > 0.f) u0 = __expf(s0 * rz0) - 1.0f;
        float s1 = sE[m0 + 8]; if (s1 > 0.f) u1 = __expf(s1 * rz1) - 1.0f;
        den0 += u0; den1 += u1;
    }
    float di0 = (1.0f / 3.0f) / den0, di1 = (1.0f / 3.0f) / den1;
    const float* vs = g_vsum + src * 256;
    long orow0 = (long)(i0 + m0) * D, orow1 = (long)(i0 + m0 + 8) * D;
    #pragma unroll
    for (int f = 0; f < 16; f++) {
        int col = ni * 128 + f * 8 + c2;
        float v00 = 0.f, v01 = 0.f, v10 = 0.f, v11 = 0.f;
        if (src == 0) {
            v00 = __bfloat162float(sQp[m0 * QLD + col]);
            v01 = __bfloat162float(sQp[m0 * QLD + col + 1]);
            v10 = __bfloat162float(sQp[(m0 + 8) * QLD + col]);
            v11 = __bfloat162float(sQp[(m0 + 8) * QLD + col + 1]);
        }
        atomicAdd(&out[orow0 + col],     (vs[col]     + acc[f][0] * rz0 + u0 * v00) * di0);
        atomicAdd(&out[orow0 + col + 1], (vs[col + 1] + acc[f][1] * rz0 + u0 * v01) * di0);
        atomicAdd(&out[orow1 + col],     (vs[col]     + acc[f][2] * rz1 + u1 * v10) * di1);
        atomicAdd(&out[orow1 + col + 1], (vs[col + 1] + acc[f][3] * rz1 + u1 * v11) * di1);
    }
}

// ---------------------------------------------------------------------------
extern "C" void kernel_launch(void* const* d_in, const int* in_sizes, int n_in,
                              void* d_out, int out_size) {
    const int*   L     = (const int*)d_in[0];
    const float* H     = (const float*)d_in[1];
    const int*   Blow  = (const int*)d_in[2];
    const float* Hlow  = (const float*)d_in[3];
    const int*   Bhigh = (const int*)d_in[4];
    const float* Hhigh = (const float*)d_in[5];
    float* out = (float*)d_out;

    cudaFuncSetAttribute(attn_kernel,
                         cudaFuncAttributeMaxDynamicSharedMemorySize, SMEM_TOTAL);

    init_kernel<<<(NQ * D + 255) / 256, 256>>>(out);
    convert_kernel<<<896, 256>>>(H, Hlow, Hhigh);
    pack_T_kernel<<<32768, 256>>>(Blow);
    attn_kernel<<<384, NTH, SMEM_TOTAL>>>(L, Bhigh, out);
}

// round 11
// speedup vs baseline: 2.3785x; 1.1582x over previous
#include <cuda_runtime.h>
#include <cuda_bf16.h>
#include <cstdint>

// ============================================================================
// Simplicial attention, single-pass linearized, uniform 64-tile jobs.
// Per source (K=V):
//   Z_i = sum_j exp(s_ij)         (unmasked)
//   u_ij ~= (e_ij/Z_i) m_ij       (order-1; src0 diagonal exact via expm1)
//   out_i = sum_src (colsum(V) + T1_i/Z_i + u_ii v_i)/(M + t1_i/Z_i + u_ii)/3
// CTA = (64-row q-tile, 4096-key chunk): 896 perfectly uniform jobs.
// T1/Z/t1 partials accumulate via global atomics; finalize divides.
// ============================================================================

#define D      256
#define QR     64
#define KT     64
#define NT     64      // key tiles per chunk
#define NTH    256
#define NQ     8192
#define SCALE  0.0625f
#define QLD    264
#define KLD    264
#define ULD    72

#define SQ_OFF  0
#define SQ_SZ   (QR * QLD * 2)            // 33792
#define K_OFF   SQ_SZ
#define K_SZ    (KT * KLD * 2)            // 33792 x2
#define U_OFF   (K_OFF + 2 * K_SZ)        // 101376
#define U_SZ    (QR * ULD * 2)            // 9216
#define SMEM_TOTAL (U_OFF + U_SZ)         // 110592 -> 2 CTAs/SM

// ---------------------------------------------------------------------------
__device__ __align__(128) __nv_bfloat16 g_kv[28672 * 256];   // 14.7 MB
__device__ __align__(128) float    g_vsum[3 * 256];
__device__ __align__(128) uint32_t g_mb1[8192L * 128];       // 4 MB, B_low^T bits
__device__ __align__(128) float    g_T1[3L * 8192 * 256];    // 25 MB partials
__device__ __align__(128) float    g_Z[3 * 8192];
__device__ __align__(128) float    g_t1[3 * 8192];
__device__ __align__(128) float    g_eii[8192];              // masked diag e

__device__ __forceinline__ uint32_t smem_u32(const void* p) {
    return (uint32_t)__cvta_generic_to_shared(p);
}
__device__ __forceinline__ void cp16(uint32_t dst, const void* src) {
    asm volatile("cp.async.cg.shared.global [%0], [%1], 16;" :: "r"(dst), "l"(src));
}
#define CP_COMMIT() asm volatile("cp.async.commit_group;" ::: "memory")
#define CP_WAIT1()  asm volatile("cp.async.wait_group 1;" ::: "memory")

__device__ __forceinline__ void ldsm_x4(uint32_t& r0, uint32_t& r1,
                                        uint32_t& r2, uint32_t& r3, uint32_t addr) {
    asm volatile("ldmatrix.sync.aligned.m8n8.x4.shared.b16 {%0,%1,%2,%3}, [%4];\n"
                 : "=r"(r0), "=r"(r1), "=r"(r2), "=r"(r3) : "r"(addr));
}
__device__ __forceinline__ void ldsm_x4_t(uint32_t& r0, uint32_t& r1,
                                          uint32_t& r2, uint32_t& r3, uint32_t addr) {
    asm volatile("ldmatrix.sync.aligned.m8n8.x4.trans.shared.b16 {%0,%1,%2,%3}, [%4];\n"
                 : "=r"(r0), "=r"(r1), "=r"(r2), "=r"(r3) : "r"(addr));
}
__device__ __forceinline__ void mma_bf16(float* d, const uint32_t* a, const uint32_t* b) {
    asm volatile(
        "mma.sync.aligned.m16n8k16.row.col.f32.bf16.bf16.f32 "
        "{%0,%1,%2,%3}, {%4,%5,%6,%7}, {%8,%9}, {%0,%1,%2,%3};\n"
        : "+f"(d[0]), "+f"(d[1]), "+f"(d[2]), "+f"(d[3])
        : "r"(a[0]), "r"(a[1]), "r"(a[2]), "r"(a[3]), "r"(b[0]), "r"(b[1]));
}

// ---------------------------------------------------------------------------
__global__ void init_kernel() {
    long idx = (long)blockIdx.x * 256 + threadIdx.x;
    if (idx < 3L * 8192 * 256) g_T1[idx] = 0.0f;
    if (idx < 3 * 8192) { g_Z[idx] = 0.0f; g_t1[idx] = 0.0f; }
    if (idx < 8192) g_eii[idx] = 0.0f;
    if (idx < 3 * 256) g_vsum[idx] = 0.0f;
}

__global__ void convert_kernel(const float* __restrict__ H,
                               const float* __restrict__ Hlow,
                               const float* __restrict__ Hhigh) {
    int r0 = blockIdx.x * 32, col = threadIdx.x;
    float acc = 0.0f;
    #pragma unroll 4
    for (int i = 0; i < 32; i++) {
        int r = r0 + i;
        float v;
        if (r < 8192)       v = H[(long)r * D + col];
        else if (r < 12288) v = Hlow[(long)(r - 8192) * D + col];
        else                v = Hhigh[(long)(r - 12288) * D + col];
        g_kv[(long)r * D + col] = __float2bfloat16(v);
        acc += v;
    }
    int src = (r0 < 8192) ? 0 : (r0 < 12288 ? 1 : 2);
    atomicAdd(&g_vsum[src * 256 + col], acc);
}

// pack B_low[4096][8192] transposed -> g_mb1[8192 rows][128 words]
__global__ void pack_T_kernel(const int* __restrict__ B) {
    __shared__ int sm[32 * 33];
    int kt = blockIdx.x & 127, it = blockIdx.x >> 7;
    int k0 = kt * 32, i0 = it * 32;
    int tid = threadIdx.x;
    #pragma unroll
    for (int s = 0; s < 4; s++) {
        int idx = tid + s * 256;
        int r = idx >> 5, c = idx & 31;
        sm[r * 33 + c] = B[(long)(k0 + r) * NQ + i0 + c];
    }
    __syncthreads();
    int w = tid >> 5, lane = tid & 31;
    #pragma unroll
    for (int q = 0; q < 4; q++) {
        int i = w * 4 + q;
        uint32_t word = __ballot_sync(0xffffffffu, sm[lane * 33 + i] != 0);
        if (lane == 0) g_mb1[(long)(i0 + i) * 128 + kt] = word;
    }
}

// ---------------------------------------------------------------------------
__global__ __launch_bounds__(NTH, 2)
void attn_kernel(const int* __restrict__ L,
                 const int* __restrict__ Bhigh) {
    extern __shared__ char smem[];
    uint32_t sb = smem_u32(smem);
    const uint32_t sQ = sb + SQ_OFF;
    __nv_bfloat16* sUp = (__nv_bfloat16*)(smem + U_OFF);

    int bid = blockIdx.x;
    int qt = bid / 7, ch = bid % 7;
    int i0 = qt * QR;

    // chunk table: 7 uniform chunks of 64 key-tiles
    int src, kvrow0, kloc0, W;
    const int* mask;
    if (ch < 2)      { src = 0; kvrow0 = ch * 4096;            kloc0 = ch * 4096;     W = 8192;  mask = L; }
    else if (ch == 2){ src = 1; kvrow0 = 8192;                 kloc0 = 0;             W = 0;     mask = L; }
    else             { src = 2; kvrow0 = 12288 + (ch-3)*4096;  kloc0 = (ch-3)*4096;   W = 16384; mask = Bhigh; }
    // src0 diagonal tile index within this chunk (or -1)
    int diag_j = -1;
    if (src == 0) { int dj = (i0 - kloc0) >> 6; if (dj >= 0 && dj < NT) diag_j = dj; }

    int tid = threadIdx.x, lane = tid & 31, w = tid >> 5;
    int mi = w & 3, ni = w >> 2;
    int g = lane >> 2, c2 = (lane & 3) << 1;
    int lr16 = lane & 15, lc8 = (lane >> 4) << 3;
    int brow = (lane & 7) + ((lane & 16) >> 1), bcol8 = lane & 8;
    int m0 = mi * 16 + g;
    int wn = w * 32;               // PV: warp-owned out-col range

    // ---- prologue: Q + K0 group, K1 group
    {
        const char* gq = (const char*)(g_kv + (long)i0 * D);
        #pragma unroll
        for (int i = 0; i < 8; i++) {
            int idx = tid + i * NTH;
            int r = idx >> 5, cc = (idx & 31) << 3;
            cp16(sQ + (uint32_t)((r * QLD + cc) * 2), gq + ((long)r * D + cc) * 2);
        }
        const char* gk = (const char*)(g_kv + (long)kvrow0 * D);
        #pragma unroll
        for (int i = 0; i < 8; i++) {
            int idx = tid + i * NTH;
            int k = idx >> 5, cc = (idx & 31) << 3;
            cp16(sb + K_OFF + (uint32_t)((k * KLD + cc) * 2), gk + ((long)k * D + cc) * 2);
        }
        CP_COMMIT();
        const char* gk1 = (const char*)(g_kv + (long)(kvrow0 + KT) * D);
        #pragma unroll
        for (int i = 0; i < 8; i++) {
            int idx = tid + i * NTH;
            int k = idx >> 5, cc = (idx & 31) << 3;
            cp16(sb + K_OFF + K_SZ + (uint32_t)((k * KLD + cc) * 2), gk1 + ((long)k * D + cc) * 2);
        }
        CP_COMMIT();
    }

    float zacc0 = 0.f, zacc1 = 0.f, t1acc0 = 0.f, t1acc1 = 0.f;
    float acc[16][4];
    #pragma unroll
    for (int f = 0; f < 16; f++) { acc[f][0]=0.f; acc[f][1]=0.f; acc[f][2]=0.f; acc[f][3]=0.f; }

    uint32_t aBase = sQ + (uint32_t)(((mi * 16 + lr16) * QLD + lc8) * 2);
    uint32_t sUo = sb + U_OFF;
    const int* mr0 = mask + (long)(i0 + m0) * W + kloc0 + ni * 32 + c2;
    const int* mr1 = mask + (long)(i0 + m0 + 8) * W + kloc0 + ni * 32 + c2;
    const uint32_t* br0 = g_mb1 + (long)(i0 + m0) * 128;
    const uint32_t* br1 = g_mb1 + (long)(i0 + m0 + 8) * 128;

    for (int j = 0; j < NT; j++) {
        CP_WAIT1();
        __syncthreads();
        uint32_t kb = sb + K_OFF + (j & 1) * K_SZ;

        // ---- mask loads (early; overlap S-GEMM)
        int2 ma[4], mb[4];
        uint64_t bt0 = 0, bt1 = 0;
        if (src == 1) {
            bt0 = *(const uint64_t*)(br0 + j * 2);
            bt1 = *(const uint64_t*)(br1 + j * 2);
        } else {
            #pragma unroll
            for (int f = 0; f < 4; f++) {
                ma[f] = *(const int2*)(mr0 + j * 64 + f * 8);
                mb[f] = *(const int2*)(mr1 + j * 64 + f * 8);
            }
        }

        // ---- S = Q K^T (64x64), proven fragment path
        float d[4][4];
        #pragma unroll
        for (int f = 0; f < 4; f++) { d[f][0]=0.f; d[f][1]=0.f; d[f][2]=0.f; d[f][3]=0.f; }
        #pragma unroll
        for (int kk = 0; kk < 16; kk++) {
            uint32_t a[4];
            ldsm_x4(a[0], a[1], a[2], a[3], aBase + kk * 32);
            #pragma unroll
            for (int jj = 0; jj < 2; jj++) {
                uint32_t b[4];
                uint32_t ba = kb + (uint32_t)(((ni * 32 + jj * 16 + brow) * KLD
                                               + kk * 16 + bcol8) * 2);
                ldsm_x4(b[0], b[1], b[2], b[3], ba);
                mma_bf16(d[2 * jj],     a, b);
                mma_bf16(d[2 * jj + 1], a, b + 2);
            }
        }

        // ---- e = exp(s*scale); w = e*mask; stash masked diag e (src0)
        bool diagTile = (j == diag_j);
        #pragma unroll
        for (int f = 0; f < 4; f++) {
            int n = ni * 32 + f * 8 + c2;
            float e0 = __expf(d[f][0] * SCALE);
            float e1 = __expf(d[f][1] * SCALE);
            float e2 = __expf(d[f][2] * SCALE);
            float e3 = __expf(d[f][3] * SCALE);
            zacc0 += e0 + e1;
            zacc1 += e2 + e3;
            bool b00, b01, b10, b11;
            if (src == 1) {
                b00 = (bt0 >> n) & 1;  b01 = (bt0 >> (n + 1)) & 1;
                b10 = (bt1 >> n) & 1;  b11 = (bt1 >> (n + 1)) & 1;
            } else {
                b00 = ma[f].x != 0;  b01 = ma[f].y != 0;
                b10 = mb[f].x != 0;  b11 = mb[f].y != 0;
            }
            if (diagTile) {
                if (m0 == n)         { g_eii[i0 + m0]     = b00 ? e0 : 0.f; b00 = false; }
                if (m0 == n + 1)     { g_eii[i0 + m0]     = b01 ? e1 : 0.f; b01 = false; }
                if (m0 + 8 == n)     { g_eii[i0 + m0 + 8] = b10 ? e2 : 0.f; b10 = false; }
                if (m0 + 8 == n + 1) { g_eii[i0 + m0 + 8] = b11 ? e3 : 0.f; b11 = false; }
            }
            float w0 = b00 ? e0 : 0.f, w1 = b01 ? e1 : 0.f;
            float w2 = b10 ? e2 : 0.f, w3 = b11 ? e3 : 0.f;
            t1acc0 += w0 + w1;
            t1acc1 += w2 + w3;
            *(__nv_bfloat162*)(sUp + m0 * ULD + n)       = __floats2bfloat162_rn(w0, w1);
            *(__nv_bfloat162*)(sUp + (m0 + 8) * ULD + n) = __floats2bfloat162_rn(w2, w3);
        }
        __syncthreads();

        // ---- T1 += W @ V: warp owns all 64 rows x 32 cols (V frags exclusive)
        #pragma unroll
        for (int kk = 0; kk < 4; kk++) {
            uint32_t bv[8];
            ldsm_x4_t(bv[0], bv[1], bv[2], bv[3],
                      kb + (uint32_t)(((kk * 16 + lr16) * KLD + wn + lc8) * 2));
            ldsm_x4_t(bv[4], bv[5], bv[6], bv[7],
                      kb + (uint32_t)(((kk * 16 + lr16) * KLD + wn + 16 + lc8) * 2));
            #pragma unroll
            for (int ms = 0; ms < 4; ms++) {
                uint32_t a[4];
                ldsm_x4(a[0], a[1], a[2], a[3],
                        sUo + (uint32_t)(((ms * 16 + lr16) * ULD + kk * 16 + lc8) * 2));
                mma_bf16(acc[ms * 4 + 0], a, bv);
                mma_bf16(acc[ms * 4 + 1], a, bv + 2);
                mma_bf16(acc[ms * 4 + 2], a, bv + 4);
                mma_bf16(acc[ms * 4 + 3], a, bv + 6);
            }
        }
        __syncthreads();

        // ---- refill buffer (j&1) with tile j+2
        if (j + 2 < NT) {
            const char* gk = (const char*)(g_kv + (long)(kvrow0 + (j + 2) * KT) * D);
            uint32_t dst = sb + K_OFF + (j & 1) * K_SZ;
            #pragma unroll
            for (int i = 0; i < 8; i++) {
                int idx = tid + i * NTH;
                int k = idx >> 5, cc = (idx & 31) << 3;
                cp16(dst + (uint32_t)((k * KLD + cc) * 2), gk + ((long)k * D + cc) * 2);
            }
        }
        CP_COMMIT();
    }

    // ---- row partials: Z and t1 (quad reduce, then global atomics)
    zacc0 += __shfl_xor_sync(~0u, zacc0, 1); zacc0 += __shfl_xor_sync(~0u, zacc0, 2);
    zacc1 += __shfl_xor_sync(~0u, zacc1, 1); zacc1 += __shfl_xor_sync(~0u, zacc1, 2);
    t1acc0 += __shfl_xor_sync(~0u, t1acc0, 1); t1acc0 += __shfl_xor_sync(~0u, t1acc0, 2);
    t1acc1 += __shfl_xor_sync(~0u, t1acc1, 1); t1acc1 += __shfl_xor_sync(~0u, t1acc1, 2);
    if ((lane & 3) == 0) {
        atomicAdd(&g_Z[src * 8192 + i0 + m0],      zacc0);
        atomicAdd(&g_Z[src * 8192 + i0 + m0 + 8],  zacc1);
        atomicAdd(&g_t1[src * 8192 + i0 + m0],     t1acc0);
        atomicAdd(&g_t1[src * 8192 + i0 + m0 + 8], t1acc1);
    }

    // ---- T1 partial atomics (unscaled; finalize applies 1/Z)
    #pragma unroll
    for (int ms = 0; ms < 4; ms++) {
        long b0 = ((long)src * 8192 + i0 + ms * 16 + g) * 256;
        #pragma unroll
        for (int f = 0; f < 4; f++) {
            int col = wn + f * 8 + c2;
            float* ac = acc[ms * 4 + f];
            atomicAdd(&g_T1[b0 + col],             ac[0]);
            atomicAdd(&g_T1[b0 + col + 1],         ac[1]);
            atomicAdd(&g_T1[b0 + 8 * 256 + col],     ac[2]);
            atomicAdd(&g_T1[b0 + 8 * 256 + col + 1], ac[3]);
        }
    }
}

// ---------------------------------------------------------------------------
__global__ void finalize_kernel(float* __restrict__ out) {
    int i = blockIdx.x, c = threadIdx.x;
    float rz0 = 1.0f / g_Z[i];
    float rz1 = 1.0f / g_Z[8192 + i];
    float rz2 = 1.0f / g_Z[16384 + i];

    // src0 diagonal: exact expm1 term (g_eii holds masked diag e, 0 if masked out)
    float s = g_eii[i];
    float u = (s > 0.f) ? (__expf(s * rz0) - 1.0f) : 0.0f;
    float v = __bfloat162float(g_kv[(long)i * 256 + c]);

    float n0 = g_vsum[c]       + g_T1[((long)0 * 8192 + i) * 256 + c] * rz0 + u * v;
    float d0 = 8192.0f  + g_t1[i] * rz0 + u;
    float n1 = g_vsum[256 + c] + g_T1[((long)1 * 8192 + i) * 256 + c] * rz1;
    float d1 = 4096.0f  + g_t1[8192 + i] * rz1;
    float n2 = g_vsum[512 + c] + g_T1[((long)2 * 8192 + i) * 256 + c] * rz2;
    float d2 = 16384.0f + g_t1[16384 + i] * rz2;

    out[(long)i * 256 + c] = (n0 / d0 + n1 / d1 + n2 / d2) * (1.0f / 3.0f);
}

// ---------------------------------------------------------------------------
extern "C" void kernel_launch(void* const* d_in, const int* in_sizes, int n_in,
                              void* d_out, int out_size) {
    const int*   L     = (const int*)d_in[0];
    const float* H     = (const float*)d_in[1];
    const int*   Blow  = (const int*)d_in[2];
    const float* Hlow  = (const float*)d_in[3];
    const int*   Bhigh = (const int*)d_in[4];
    const float* Hhigh = (const float*)d_in[5];
    float* out = (float*)d_out;

    cudaFuncSetAttribute(attn_kernel,
                         cudaFuncAttributeMaxDynamicSharedMemorySize, SMEM_TOTAL);

    init_kernel<<<24576, 256>>>();
    convert_kernel<<<896, 256>>>(H, Hlow, Hhigh);
    pack_T_kernel<<<32768, 256>>>(Blow);
    attn_kernel<<<896, NTH, SMEM_TOTAL>>>(L, Bhigh);
    finalize_kernel<<<8192, 256>>>(out);
}

// round 12
// speedup vs baseline: 2.3837x; 1.0022x over previous
#include <cuda_runtime.h>
#include <cuda_bf16.h>
#include <cstdint>

// ============================================================================
// Simplicial attention, single-pass linearized, uniform 64-tile jobs,
// cross-tile software pipeline: exp(j) | S(j+1)+PV(j) | refill(j+2).
// Per source (K=V):
//   Z_i = sum_j exp(s_ij)         (unmasked)
//   u_ij ~= (e_ij/Z_i) m_ij       (order-1; src0 diagonal exact via expm1)
//   out_i = sum_src (colsum(V) + T1_i/Z_i + u_ii v_i)/(M + t1_i/Z_i + u_ii)/3
// ============================================================================

#define D      256
#define QR     64
#define KT     64
#define NT     64
#define NTH    256
#define NQ     8192
#define SCALE  0.0625f
#define QLD    264
#define KLD    264
#define ULD    72

#define SQ_OFF  0
#define SQ_SZ   (QR * QLD * 2)            // 33792
#define K_OFF   SQ_SZ
#define K_SZ    (KT * KLD * 2)            // 33792 x2
#define U_OFF   (K_OFF + 2 * K_SZ)        // 101376
#define U_SZ    (QR * ULD * 2)            // 9216
#define SMEM_TOTAL (U_OFF + U_SZ)         // 110592 -> 2 CTAs/SM

// ---------------------------------------------------------------------------
__device__ __align__(128) __nv_bfloat16 g_kv[28672 * 256];   // 14.7 MB
__device__ __align__(128) float    g_vsum[3 * 256];
__device__ __align__(128) uint32_t g_mb1[8192L * 128];       // 4 MB, B_low^T bits
__device__ __align__(128) float    g_T1[3L * 8192 * 256];    // 25 MB partials
__device__ __align__(128) float    g_Z[3 * 8192];
__device__ __align__(128) float    g_t1[3 * 8192];
__device__ __align__(128) float    g_eii[8192];              // masked diag e

__device__ __forceinline__ uint32_t smem_u32(const void* p) {
    return (uint32_t)__cvta_generic_to_shared(p);
}
__device__ __forceinline__ void cp16(uint32_t dst, const void* src) {
    asm volatile("cp.async.cg.shared.global [%0], [%1], 16;" :: "r"(dst), "l"(src));
}
#define CP_COMMIT() asm volatile("cp.async.commit_group;" ::: "memory")
#define CP_WAIT0()  asm volatile("cp.async.wait_group 0;" ::: "memory")
#define CP_WAIT1()  asm volatile("cp.async.wait_group 1;" ::: "memory")

__device__ __forceinline__ void ldsm_x4(uint32_t& r0, uint32_t& r1,
                                        uint32_t& r2, uint32_t& r3, uint32_t addr) {
    asm volatile("ldmatrix.sync.aligned.m8n8.x4.shared.b16 {%0,%1,%2,%3}, [%4];\n"
                 : "=r"(r0), "=r"(r1), "=r"(r2), "=r"(r3) : "r"(addr));
}
__device__ __forceinline__ void ldsm_x4_t(uint32_t& r0, uint32_t& r1,
                                          uint32_t& r2, uint32_t& r3, uint32_t addr) {
    asm volatile("ldmatrix.sync.aligned.m8n8.x4.trans.shared.b16 {%0,%1,%2,%3}, [%4];\n"
                 : "=r"(r0), "=r"(r1), "=r"(r2), "=r"(r3) : "r"(addr));
}
__device__ __forceinline__ void mma_bf16(float* d, const uint32_t* a, const uint32_t* b) {
    asm volatile(
        "mma.sync.aligned.m16n8k16.row.col.f32.bf16.bf16.f32 "
        "{%0,%1,%2,%3}, {%4,%5,%6,%7}, {%8,%9}, {%0,%1,%2,%3};\n"
        : "+f"(d[0]), "+f"(d[1]), "+f"(d[2]), "+f"(d[3])
        : "r"(a[0]), "r"(a[1]), "r"(a[2]), "r"(a[3]), "r"(b[0]), "r"(b[1]));
}

// S = Q K^T 64x64 fragment path (proven round-0 layout)
__device__ __forceinline__ void sgemm_tile(uint32_t aBase, uint32_t kb,
                                           int ni, int brow, int bcol8,
                                           float d[4][4]) {
    #pragma unroll
    for (int f = 0; f < 4; f++) { d[f][0]=0.f; d[f][1]=0.f; d[f][2]=0.f; d[f][3]=0.f; }
    #pragma unroll
    for (int kk = 0; kk < 16; kk++) {
        uint32_t a[4];
        ldsm_x4(a[0], a[1], a[2], a[3], aBase + kk * 32);
        #pragma unroll
        for (int jj = 0; jj < 2; jj++) {
            uint32_t b[4];
            uint32_t ba = kb + (uint32_t)(((ni * 32 + jj * 16 + brow) * KLD
                                           + kk * 16 + bcol8) * 2);
            ldsm_x4(b[0], b[1], b[2], b[3], ba);
            mma_bf16(d[2 * jj],     a, b);
            mma_bf16(d[2 * jj + 1], a, b + 2);
        }
    }
}

// T1 += W @ V: warp owns all 64 rows x 32 out-cols
__device__ __forceinline__ void pv_tile(uint32_t sUo, uint32_t kb,
                                        int wn, int lr16, int lc8,
                                        float acc[16][4]) {
    #pragma unroll
    for (int kk = 0; kk < 4; kk++) {
        uint32_t bv[8];
        ldsm_x4_t(bv[0], bv[1], bv[2], bv[3],
                  kb + (uint32_t)(((kk * 16 + lr16) * KLD + wn + lc8) * 2));
        ldsm_x4_t(bv[4], bv[5], bv[6], bv[7],
                  kb + (uint32_t)(((kk * 16 + lr16) * KLD + wn + 16 + lc8) * 2));
        #pragma unroll
        for (int ms = 0; ms < 4; ms++) {
            uint32_t a[4];
            ldsm_x4(a[0], a[1], a[2], a[3],
                    sUo + (uint32_t)(((ms * 16 + lr16) * ULD + kk * 16 + lc8) * 2));
            mma_bf16(acc[ms * 4 + 0], a, bv);
            mma_bf16(acc[ms * 4 + 1], a, bv + 2);
            mma_bf16(acc[ms * 4 + 2], a, bv + 4);
            mma_bf16(acc[ms * 4 + 3], a, bv + 6);
        }
    }
}

// ---------------------------------------------------------------------------
__global__ void init_kernel() {
    long idx = (long)blockIdx.x * 256 + threadIdx.x;
    if (idx < 3L * 8192 * 256) g_T1[idx] = 0.0f;
    if (idx < 3 * 8192) { g_Z[idx] = 0.0f; g_t1[idx] = 0.0f; }
    if (idx < 8192) g_eii[idx] = 0.0f;
    if (idx < 3 * 256) g_vsum[idx] = 0.0f;
}

__global__ void convert_kernel(const float* __restrict__ H,
                               const float* __restrict__ Hlow,
                               const float* __restrict__ Hhigh) {
    int r0 = blockIdx.x * 32, col = threadIdx.x;
    float acc = 0.0f;
    #pragma unroll 4
    for (int i = 0; i < 32; i++) {
        int r = r0 + i;
        float v;
        if (r < 8192)       v = H[(long)r * D + col];
        else if (r < 12288) v = Hlow[(long)(r - 8192) * D + col];
        else                v = Hhigh[(long)(r - 12288) * D + col];
        g_kv[(long)r * D + col] = __float2bfloat16(v);
        acc += v;
    }
    int src = (r0 < 8192) ? 0 : (r0 < 12288 ? 1 : 2);
    atomicAdd(&g_vsum[src * 256 + col], acc);
}

// pack B_low[4096][8192] transposed -> g_mb1[8192 rows][128 words]
__global__ void pack_T_kernel(const int* __restrict__ B) {
    __shared__ int sm[32 * 33];
    int kt = blockIdx.x & 127, it = blockIdx.x >> 7;
    int k0 = kt * 32, i0 = it * 32;
    int tid = threadIdx.x;
    #pragma unroll
    for (int s = 0; s < 4; s++) {
        int idx = tid + s * 256;
        int r = idx >> 5, c = idx & 31;
        sm[r * 33 + c] = B[(long)(k0 + r) * NQ + i0 + c];
    }
    __syncthreads();
    int w = tid >> 5, lane = tid & 31;
    #pragma unroll
    for (int q = 0; q < 4; q++) {
        int i = w * 4 + q;
        uint32_t word = __ballot_sync(0xffffffffu, sm[lane * 33 + i] != 0);
        if (lane == 0) g_mb1[(long)(i0 + i) * 128 + kt] = word;
    }
}

// ---------------------------------------------------------------------------
__global__ __launch_bounds__(NTH, 2)
void attn_kernel(const int* __restrict__ L,
                 const int* __restrict__ Bhigh) {
    extern __shared__ char smem[];
    uint32_t sb = smem_u32(smem);
    const uint32_t sQ = sb + SQ_OFF;
    __nv_bfloat16* sUp = (__nv_bfloat16*)(smem + U_OFF);

    int bid = blockIdx.x;
    int qt = bid / 7, ch = bid % 7;
    int i0 = qt * QR;

    int src, kvrow0, kloc0, W;
    const int* mask;
    if (ch < 2)      { src = 0; kvrow0 = ch * 4096;            kloc0 = ch * 4096;     W = 8192;  mask = L; }
    else if (ch == 2){ src = 1; kvrow0 = 8192;                 kloc0 = 0;             W = 0;     mask = L; }
    else             { src = 2; kvrow0 = 12288 + (ch-3)*4096;  kloc0 = (ch-3)*4096;   W = 16384; mask = Bhigh; }
    int diag_j = -1;
    if (src == 0) { int dj = (i0 - kloc0) >> 6; if (dj >= 0 && dj < NT) diag_j = dj; }

    int tid = threadIdx.x, lane = tid & 31, w = tid >> 5;
    int mi = w & 3, ni = w >> 2;
    int g = lane >> 2, c2 = (lane & 3) << 1;
    int lr16 = lane & 15, lc8 = (lane >> 4) << 3;
    int brow = (lane & 7) + ((lane & 16) >> 1), bcol8 = lane & 8;
    int m0 = mi * 16 + g;
    int wn = w * 32;

    // ---- prologue: Q + K0 group, K1 group
    {
        const char* gq = (const char*)(g_kv + (long)i0 * D);
        #pragma unroll
        for (int i = 0; i < 8; i++) {
            int idx = tid + i * NTH;
            int r = idx >> 5, cc = (idx & 31) << 3;
            cp16(sQ + (uint32_t)((r * QLD + cc) * 2), gq + ((long)r * D + cc) * 2);
        }
        const char* gk = (const char*)(g_kv + (long)kvrow0 * D);
        #pragma unroll
        for (int i = 0; i < 8; i++) {
            int idx = tid + i * NTH;
            int k = idx >> 5, cc = (idx & 31) << 3;
            cp16(sb + K_OFF + (uint32_t)((k * KLD + cc) * 2), gk + ((long)k * D + cc) * 2);
        }
        CP_COMMIT();
        const char* gk1 = (const char*)(g_kv + (long)(kvrow0 + KT) * D);
        #pragma unroll
        for (int i = 0; i < 8; i++) {
            int idx = tid + i * NTH;
            int k = idx >> 5, cc = (idx & 31) << 3;
            cp16(sb + K_OFF + K_SZ + (uint32_t)((k * KLD + cc) * 2), gk1 + ((long)k * D + cc) * 2);
        }
        CP_COMMIT();
    }

    float zacc0 = 0.f, zacc1 = 0.f, t1acc0 = 0.f, t1acc1 = 0.f;
    float acc[16][4];
    #pragma unroll
    for (int f = 0; f < 16; f++) { acc[f][0]=0.f; acc[f][1]=0.f; acc[f][2]=0.f; acc[f][3]=0.f; }

    uint32_t aBase = sQ + (uint32_t)(((mi * 16 + lr16) * QLD + lc8) * 2);
    uint32_t sUo = sb + U_OFF;
    const int* mr0 = mask + (long)(i0 + m0) * W + kloc0 + ni * 32 + c2;
    const int* mr1 = mask + (long)(i0 + m0 + 8) * W + kloc0 + ni * 32 + c2;
    const uint32_t* br0 = g_mb1 + (long)(i0 + m0) * 128;
    const uint32_t* br1 = g_mb1 + (long)(i0 + m0 + 8) * 128;

    // mask regs (prefetched one tile ahead)
    int2 ma[4], mb[4];
    uint64_t bt0 = 0, bt1 = 0;
    // mask(0)
    if (src == 1) {
        bt0 = *(const uint64_t*)(br0);
        bt1 = *(const uint64_t*)(br1);
    } else {
        #pragma unroll
        for (int f = 0; f < 4; f++) {
            ma[f] = *(const int2*)(mr0 + f * 8);
            mb[f] = *(const int2*)(mr1 + f * 8);
        }
    }

    CP_WAIT1();          // Q + K0 ready (K1 may still be in flight)
    __syncthreads();

    float d[4][4];
    sgemm_tile(aBase, sb + K_OFF, ni, brow, bcol8, d);   // S(0) from buf0

    for (int j = 0; j < NT; j++) {
        // ---- exp(j): d -> w, masks, U store, z/t1, diag
        bool diagTile = (j == diag_j);
        #pragma unroll
        for (int f = 0; f < 4; f++) {
            int n = ni * 32 + f * 8 + c2;
            float e0 = __expf(d[f][0] * SCALE);
            float e1 = __expf(d[f][1] * SCALE);
            float e2 = __expf(d[f][2] * SCALE);
            float e3 = __expf(d[f][3] * SCALE);
            zacc0 += e0 + e1;
            zacc1 += e2 + e3;
            bool b00, b01, b10, b11;
            if (src == 1) {
                b00 = (bt0 >> n) & 1;  b01 = (bt0 >> (n + 1)) & 1;
                b10 = (bt1 >> n) & 1;  b11 = (bt1 >> (n + 1)) & 1;
            } else {
                b00 = ma[f].x != 0;  b01 = ma[f].y != 0;
                b10 = mb[f].x != 0;  b11 = mb[f].y != 0;
            }
            if (diagTile) {
                if (m0 == n)         { g_eii[i0 + m0]     = b00 ? e0 : 0.f; b00 = false; }
                if (m0 == n + 1)     { g_eii[i0 + m0]     = b01 ? e1 : 0.f; b01 = false; }
                if (m0 + 8 == n)     { g_eii[i0 + m0 + 8] = b10 ? e2 : 0.f; b10 = false; }
                if (m0 + 8 == n + 1) { g_eii[i0 + m0 + 8] = b11 ? e3 : 0.f; b11 = false; }
            }
            float w0 = b00 ? e0 : 0.f, w1 = b01 ? e1 : 0.f;
            float w2 = b10 ? e2 : 0.f, w3 = b11 ? e3 : 0.f;
            t1acc0 += w0 + w1;
            t1acc1 += w2 + w3;
            *(__nv_bfloat162*)(sUp + m0 * ULD + n)       = __floats2bfloat162_rn(w0, w1);
            *(__nv_bfloat162*)(sUp + (m0 + 8) * ULD + n) = __floats2bfloat162_rn(w2, w3);
        }

        CP_WAIT0();           // K(j+1) resident
        __syncthreads();      // U(j) visible; PV(j-1) done with buf((j+1)&1)

        // ---- prefetch masks(j+1) (latency hidden under S+PV)
        if (j + 1 < NT) {
            if (src == 1) {
                bt0 = *(const uint64_t*)(br0 + (j + 1) * 2);
                bt1 = *(const uint64_t*)(br1 + (j + 1) * 2);
            } else {
                #pragma unroll
                for (int f = 0; f < 4; f++) {
                    ma[f] = *(const int2*)(mr0 + (j + 1) * 64 + f * 8);
                    mb[f] = *(const int2*)(mr1 + (j + 1) * 64 + f * 8);
                }
            }
        }

        // ---- S(j+1) and PV(j): independent, back-to-back (scheduler overlaps)
        if (j + 1 < NT)
            sgemm_tile(aBase, sb + K_OFF + ((j + 1) & 1) * K_SZ, ni, brow, bcol8, d);
        pv_tile(sUo, sb + K_OFF + (j & 1) * K_SZ, wn, lr16, lc8, acc);

        __syncthreads();      // PV(j) done with buf(j&1) and U(j)

        // ---- refill buf(j&1) with tile j+2
        if (j + 2 < NT) {
            const char* gk = (const char*)(g_kv + (long)(kvrow0 + (j + 2) * KT) * D);
            uint32_t dst = sb + K_OFF + (j & 1) * K_SZ;
            #pragma unroll
            for (int i = 0; i < 8; i++) {
                int idx = tid + i * NTH;
                int k = idx >> 5, cc = (idx & 31) << 3;
                cp16(dst + (uint32_t)((k * KLD + cc) * 2), gk + ((long)k * D + cc) * 2);
            }
        }
        CP_COMMIT();
    }

    // ---- row partials: Z and t1 (quad reduce, then global atomics)
    zacc0 += __shfl_xor_sync(~0u, zacc0, 1); zacc0 += __shfl_xor_sync(~0u, zacc0, 2);
    zacc1 += __shfl_xor_sync(~0u, zacc1, 1); zacc1 += __shfl_xor_sync(~0u, zacc1, 2);
    t1acc0 += __shfl_xor_sync(~0u, t1acc0, 1); t1acc0 += __shfl_xor_sync(~0u, t1acc0, 2);
    t1acc1 += __shfl_xor_sync(~0u, t1acc1, 1); t1acc1 += __shfl_xor_sync(~0u, t1acc1, 2);
    if ((lane & 3) == 0) {
        atomicAdd(&g_Z[src * 8192 + i0 + m0],      zacc0);
        atomicAdd(&g_Z[src * 8192 + i0 + m0 + 8],  zacc1);
        atomicAdd(&g_t1[src * 8192 + i0 + m0],     t1acc0);
        atomicAdd(&g_t1[src * 8192 + i0 + m0 + 8], t1acc1);
    }

    // ---- T1 partial atomics (unscaled; finalize applies 1/Z)
    #pragma unroll
    for (int ms = 0; ms < 4; ms++) {
        long b0 = ((long)src * 8192 + i0 + ms * 16 + g) * 256;
        #pragma unroll
        for (int f = 0; f < 4; f++) {
            int col = wn + f * 8 + c2;
            float* ac = acc[ms * 4 + f];
            atomicAdd(&g_T1[b0 + col],               ac[0]);
            atomicAdd(&g_T1[b0 + col + 1],           ac[1]);
            atomicAdd(&g_T1[b0 + 8 * 256 + col],     ac[2]);
            atomicAdd(&g_T1[b0 + 8 * 256 + col + 1], ac[3]);
        }
    }
}

// ---------------------------------------------------------------------------
__global__ void finalize_kernel(float* __restrict__ out) {
    int i = blockIdx.x, c = threadIdx.x;
    float rz0 = 1.0f / g_Z[i];
    float rz1 = 1.0f / g_Z[8192 + i];
    float rz2 = 1.0f / g_Z[16384 + i];

    float s = g_eii[i];
    float u = (s > 0.f) ? (__expf(s * rz0) - 1.0f) : 0.0f;
    float v = __bfloat162float(g_kv[(long)i * 256 + c]);

    float n0 = g_vsum[c]       + g_T1[((long)0 * 8192 + i) * 256 + c] * rz0 + u * v;
    float d0 = 8192.0f  + g_t1[i] * rz0 + u;
    float n1 = g_vsum[256 + c] + g_T1[((long)1 * 8192 + i) * 256 + c] * rz1;
    float d1 = 4096.0f  + g_t1[8192 + i] * rz1;
    float n2 = g_vsum[512 + c] + g_T1[((long)2 * 8192 + i) * 256 + c] * rz2;
    float d2 = 16384.0f + g_t1[16384 + i] * rz2;

    out[(long)i * 256 + c] = (n0 / d0 + n1 / d1 + n2 / d2) * (1.0f / 3.0f);
}

// ---------------------------------------------------------------------------
extern "C" void kernel_launch(void* const* d_in, const int* in_sizes, int n_in,
                              void* d_out, int out_size) {
    const int*   L     = (const int*)d_in[0];
    const float* H     = (const float*)d_in[1];
    const int*   Blow  = (const int*)d_in[2];
    const float* Hlow  = (const float*)d_in[3];
    const int*   Bhigh = (const int*)d_in[4];
    const float* Hhigh = (const float*)d_in[5];
    float* out = (float*)d_out;

    cudaFuncSetAttribute(attn_kernel,
                         cudaFuncAttributeMaxDynamicSharedMemorySize, SMEM_TOTAL);

    init_kernel<<<24576, 256>>>();
    convert_kernel<<<896, 256>>>(H, Hlow, Hhigh);
    pack_T_kernel<<<32768, 256>>>(Blow);
    attn_kernel<<<896, NTH, SMEM_TOTAL>>>(L, Bhigh);
    finalize_kernel<<<8192, 256>>>(out);
}